// round 14
// baseline (speedup 1.0000x reference)
#include <cuda_runtime.h>
#include <cuda_bf16.h>
#include <cuda_fp16.h>
#include <cuda_fp8.h>
#include <math.h>
#include <stdint.h>

#define D        512
#define KK       32
#define PP       528
#define MB       128               // rows per CTA
#define KCH      64
#define NCHUNK   9
#define NTHREADS 512

#define H_STRIDE 592               // 37*16
#define ZQ_STRIDE 272              // 17*16
#define U_STRIDE 80
#define UQ_BYTES  (128 * U_STRIDE)      // 10240
#define CT_STRIDE 129              // coordsT word stride (129 mod 32 == 1)
#define ES_STRIDE 528              // epilogue stage row bytes

// ---------- smem ----------
#define SM_GID   0                 // 128 int
#define SM_KERN  512               // 128 f
#define SM_CHG   1024              // 512 f
#define SM_ZMU   3072              // 512 f
#define SM_LUT   5120              // 144 u16 (288B, pad 512)
#define SM_PBUF  5632              // 512 f
#define SM_COORD 7680              // 32*129*4 = 16512
#define SM_R     24192             // phase1 ZQ(34816)+UQ(2*10240) | phase2 H(75776)
#define SM_UQ    59008             // SM_R + 34816
#define SM_TOTAL 99968

__device__ float g_change[D];
__device__ float g_zmu[D];
__device__ float g_xcU[KK];
__device__ float g_dU[KK];
__device__ __align__(8) unsigned short g_wlut[144];            // i0 | (i1base<<8)
__device__ __align__(16) unsigned char g_Ubf[512 * U_STRIDE];
// V fragments, word-repacked to match H smem layout
__device__ __align__(16) unsigned char g_Vfrag[18 * 16384];    // 288KB

__device__ __forceinline__ uint32_t smem_u32(const void* p) {
    uint32_t a;
    asm("{ .reg .u64 t; cvta.to.shared.u64 t, %1; cvt.u32.u64 %0, t; }" : "=r"(a) : "l"(p));
    return a;
}
__device__ __forceinline__ void ldsm4(uint32_t* r, uint32_t a) {
    asm volatile("ldmatrix.sync.aligned.m8n8.x4.shared.b16 {%0,%1,%2,%3}, [%4];"
                 : "=r"(r[0]), "=r"(r[1]), "=r"(r[2]), "=r"(r[3]) : "r"(a));
}
__device__ __forceinline__ void ldsm4t(uint32_t* r, uint32_t a) {
    asm volatile("ldmatrix.sync.aligned.m8n8.x4.trans.shared.b16 {%0,%1,%2,%3}, [%4];"
                 : "=r"(r[0]), "=r"(r[1]), "=r"(r[2]), "=r"(r[3]) : "r"(a));
}
__device__ __forceinline__ void mma16816(float* c, const uint32_t* a, const uint32_t* b) {
    asm volatile("mma.sync.aligned.m16n8k16.row.col.f32.bf16.bf16.f32 "
                 "{%0,%1,%2,%3}, {%4,%5,%6,%7}, {%8,%9}, {%0,%1,%2,%3};"
                 : "+f"(c[0]), "+f"(c[1]), "+f"(c[2]), "+f"(c[3])
                 : "r"(a[0]), "r"(a[1]), "r"(a[2]), "r"(a[3]), "r"(b[0]), "r"(b[1]));
}
__device__ __forceinline__ void mma8h(uint32_t* c, const uint32_t* a, uint32_t b0, uint32_t b1) {
    asm volatile("mma.sync.aligned.m16n8k32.row.col.f16.e4m3.e4m3.f16 "
                 "{%0,%1}, {%2,%3,%4,%5}, {%6,%7}, {%0,%1};"
                 : "+r"(c[0]), "+r"(c[1])
                 : "r"(a[0]), "r"(a[1]), "r"(a[2]), "r"(a[3]), "r"(b0), "r"(b1));
}
__device__ __forceinline__ uint32_t pack4_e4m3(float f0, float f1, float f2, float f3) {
    uint32_t r;
    asm("{\n\t.reg .b16 lo, hi;\n\t"
        "cvt.rn.satfinite.e4m3x2.f32 lo, %2, %1;\n\t"
        "cvt.rn.satfinite.e4m3x2.f32 hi, %4, %3;\n\t"
        "mov.b32 %0, {lo, hi};\n\t}"
        : "=r"(r) : "f"(f0), "f"(f1), "f"(f2), "f"(f3));
    return r;
}
__device__ __forceinline__ void cp16(uint32_t saddr, const void* g) {
    asm volatile("cp.async.cg.shared.global [%0], [%1], 16;" :: "r"(saddr), "l"(g));
}
__device__ __forceinline__ void cp_commit() {
    asm volatile("cp.async.commit_group;" ::: "memory");
}
template <int N>
__device__ __forceinline__ void cp_wait() {
    asm volatile("cp.async.wait_group %0;" :: "n"(N) : "memory");
}

// word g -> (i0, i1base, pstart). words are 4-consecutive runs inside triu rows.
__device__ __forceinline__ void wordinfo(int g, int* i0, int* i1b, int* pstart) {
    int acc = 0, rs = 0;
    #pragma unroll 1
    for (int i = 0; i < 32; ++i) {
        int wr = (35 - i) >> 2;            // words in row i (len 32-i)
        if (g < acc + wr) {
            int k = g - acc;
            *i0 = i;
            *i1b = i + 4 * k;
            *pstart = rs + 4 * k;
            return;
        }
        acc += wr;
        rs += 32 - i;
    }
    *i0 = 0; *i1b = 32; *pstart = 0;
}

// ===================== prep =====================
__global__ void prep_kernel(const float* __restrict__ U,
                            const float* __restrict__ V,
                            const float* __restrict__ zmu,
                            const float* __restrict__ xc) {
    int b = blockIdx.x, t = threadIdx.x;
    if (b < 288) {
        int idx = b * 256 + t;                 // one fragment u32 word
        int l    = (idx >> 2) & 31;
        int jj   = idx & 3;
        int q    = (idx >> 7) & 1;
        int ks   = (idx >> 8) & 1;
        int ngrp = (idx >> 9) & 7;
        int tt   = idx >> 12;
        int i    = 8 * jj + (l >> 2);
        int nl   = ngrp * 32 + q * 16 + (i & 7) + 8 * ((i >> 4) & 1);
        int koff = ((i >> 3) & 1) * 16 + ks * 32 + (l & 3) * 4;
        int c  = tt % NCHUNK, np = tt / NCHUNK;
        int d  = np * 256 + nl;
        int g  = (c * KCH + koff) >> 2;        // word index (koff multiple of 4)
        int i0, i1b, ps;
        wordinfo(g, &i0, &i1b, &ps);
        float f[4];
        #pragma unroll
        for (int byte = 0; byte < 4; ++byte)
            f[byte] = (i1b + byte < 32) ? V[(size_t)d * PP + ps + byte] * 256.f : 0.f;
        *(uint32_t*)(g_Vfrag + (size_t)idx * 4) = pack4_e4m3(f[0], f[1], f[2], f[3]);
        return;
    }
    if (b < 368) {
        int e = (b - 288) * 256 + t;
        int k = e / 40, n = e - k * 40;
        float v = (n < KK) ? U[k * KK + n] : 0.f;
        *(__nv_bfloat16*)(g_Ubf + k * U_STRIDE + n * 2) = __float2bfloat16(v);
        return;
    }
    __shared__ float pa[256], pb[256], sdiff[KK];
    {
        int j = t & 31, seg = t >> 5;
        float a = 0.f, bb = 0.f;
        for (int i = 0; i < 64; ++i) {
            int d = seg * 64 + i;
            float u = U[d * KK + j];
            a = fmaf(zmu[d], u, a);
            bb = fmaf(xc[d], u, bb);
        }
        pa[t] = a; pb[t] = bb;
    }
    __syncthreads();
    if (t < KK) {
        float sa = 0.f, sb = 0.f;
        for (int s = 0; s < 8; ++s) { sa += pa[s * 32 + t]; sb += pb[s * 32 + t]; }
        g_xcU[t] = sb;
        g_dU[t]  = sb - sa;
        sdiff[t] = sb - sa;
    }
    __syncthreads();
    for (int d = t; d < D; d += 256) {
        float s = 0.f;
        for (int j = 0; j < KK; ++j) s = fmaf(sdiff[j], U[d * KK + j], s);
        g_change[d] = xc[d] - zmu[d] - s;
        g_zmu[d] = zmu[d];
    }
    if (t < 144) {
        int i0, i1b, ps;
        wordinfo(t, &i0, &i1b, &ps);
        g_wlut[t] = (unsigned short)(i0 | (i1b << 8));
    }
}

// ===================== fused main kernel (M=128, occ 2) ==========
__global__ __launch_bounds__(NTHREADS, 2)
void glayer_fused(const float* __restrict__ Z_all,
                  const int*   __restrict__ choice,
                  float*       __restrict__ out,
                  int Nc) {
    extern __shared__ __align__(16) char sm[];
    const uint32_t smb = smem_u32(sm);
    int*   gid    = (int*)(sm + SM_GID);
    float* kern   = (float*)(sm + SM_KERN);
    float* chg    = (float*)(sm + SM_CHG);
    float* zmus   = (float*)(sm + SM_ZMU);
    float* pbuf   = (float*)(sm + SM_PBUF);
    float* coords = (float*)(sm + SM_COORD);   // coordsT[j][m], stride 129 words

    const int tid = threadIdx.x;
    const int wid = tid >> 5;
    const int lid = tid & 31;
    const int n0  = blockIdx.x * MB;

    // U quarter 0 async copy up front
    {
        const char* usrc = (const char*)g_Ubf;
        if (tid < UQ_BYTES / 16) cp16(smb + SM_UQ + tid * 16, usrc + (size_t)tid * 16);
        if (tid < UQ_BYTES / 16 - 512)
            cp16(smb + SM_UQ + (tid + 512) * 16, usrc + (size_t)(tid + 512) * 16);
        cp_commit();
    }

    if (tid < MB) {
        int n = n0 + tid;
        gid[tid] = (n < Nc) ? choice[n] : -1;
    }
    chg[tid]  = g_change[tid];
    zmus[tid] = g_zmu[tid];
    if (tid < 72) ((uint32_t*)(sm + SM_LUT))[tid] = ((const uint32_t*)g_wlut)[tid];
    __syncthreads();

    // ---- phase 1: gather in 4 k-quarters + ZU mma (16 warps) ----
    const int r  = tid >> 2, s4 = tid & 3;          // 4 threads/row, 128 rows
    const int g  = gid[r];
    const float4* zrowg = (const float4*)(Z_all + (size_t)(g < 0 ? 0 : g) * D) + s4 * 8;
    char* zrow = sm + SM_R + r * ZQ_STRIDE + s4 * 64;

    const int zr0 = (wid & 7) * 16;
    const int zch = wid >> 3;
    const uint32_t zbase = smb + SM_R + (uint32_t)(zr0 + (lid & 15)) * ZQ_STRIDE +
                           (uint32_t)((lid >> 4) * 16);
    const uint32_t ulane = (uint32_t)((lid & 7) + 8 * ((lid >> 3) & 1)) * U_STRIDE +
                           (uint32_t)(zch * 16 + 8 * (lid >> 4)) * 2;

    float zu[2][4];
    #pragma unroll
    for (int i = 0; i < 2; ++i)
        #pragma unroll
        for (int j = 0; j < 4; ++j) zu[i][j] = 0.f;

    float accn = 0.f;
    for (int q = 0; q < 4; ++q) {
        #pragma unroll
        for (int i = 0; i < 8; ++i) {
            float4 z = make_float4(0.f, 0.f, 0.f, 0.f);
            if (g >= 0) z = zrowg[q * 32 + i];
            int d0 = q * 128 + s4 * 32 + i * 4;
            float a0 = z.x - zmus[d0], a1 = z.y - zmus[d0 + 1];
            float a2 = z.z - zmus[d0 + 2], a3 = z.w - zmus[d0 + 3];
            accn = fmaf(a0, a0, fmaf(a1, a1, fmaf(a2, a2, fmaf(a3, a3, accn))));
            __nv_bfloat162 p0 = __floats2bfloat162_rn(z.x, z.y);
            __nv_bfloat162 p1 = __floats2bfloat162_rn(z.z, z.w);
            *(uint32_t*)(zrow + i * 8)     = *(uint32_t*)&p0;
            *(uint32_t*)(zrow + i * 8 + 4) = *(uint32_t*)&p1;
        }
        if (q == 3) pbuf[tid] = accn;
        if (q < 3) {
            const char* usrc = (const char*)g_Ubf + (size_t)(q + 1) * UQ_BYTES;
            uint32_t ud = smb + SM_UQ + (uint32_t)(((q + 1) & 1) * UQ_BYTES);
            if (tid < UQ_BYTES / 16) cp16(ud + tid * 16, usrc + (size_t)tid * 16);
            if (tid < UQ_BYTES / 16 - 512)
                cp16(ud + (tid + 512) * 16, usrc + (size_t)(tid + 512) * 16);
            cp_commit();
            cp_wait<1>();
        } else {
            cp_wait<0>();
        }
        __syncthreads();
        {
            uint32_t ub = smb + SM_UQ + (uint32_t)((q & 1) * UQ_BYTES) + ulane;
            #pragma unroll
            for (int ks = 0; ks < 8; ++ks) {
                uint32_t a[4], b[4];
                ldsm4(a, zbase + (uint32_t)(ks * 32));
                ldsm4t(b, ub + (uint32_t)(ks * 16) * U_STRIDE);
                mma16816(zu[0], a, b);
                mma16816(zu[1], a, b + 2);
            }
        }
        __syncthreads();
    }

    // coordsT[c][m] = ZU - xcU
    {
        int r0 = zr0 + (lid >> 2);
        int c0 = (lid & 3) * 2;
        #pragma unroll
        for (int nt = 0; nt < 2; ++nt) {
            int c = zch * 16 + nt * 8 + c0;
            coords[c * CT_STRIDE + r0]           = zu[nt][0] - g_xcU[c];
            coords[(c + 1) * CT_STRIDE + r0]     = zu[nt][1] - g_xcU[c + 1];
            coords[c * CT_STRIDE + r0 + 8]       = zu[nt][2] - g_xcU[c];
            coords[(c + 1) * CT_STRIDE + r0 + 8] = zu[nt][3] - g_xcU[c + 1];
        }
    }
    __syncthreads();

    // ---- secant (warps 0..3) || H build (warps 4..15) ----
    if (tid < MB) {
        float un = 0.f;
        #pragma unroll
        for (int j = 0; j < KK; ++j) {
            float v = coords[j * CT_STRIDE + tid] + g_dU[j];
            un = fmaf(v, v, un);
        }
        float zn = pbuf[4 * tid] + pbuf[4 * tid + 1] + pbuf[4 * tid + 2] + pbuf[4 * tid + 3];
        float C = zn - un;
        float E = __expf(-0.01f * un);
        float x_m2 = C * 0.999f;
        float x_m1 = C;
        bool done = false;
        for (int it = 0; it < 100; ++it) {
            if (done) break;
            float t1 = 1.f - E * __expf(-0.01f * x_m1);
            float f1 = t1 * t1 * x_m1 - C;
            float t2 = 1.f - E * __expf(-0.01f * x_m2);
            float f2 = t2 * t2 * x_m2 - C;
            float fd = f1 - f2;
            if (fabsf(fd) < 1e-6f) fd = (fd >= 0.f) ? 1e-6f : -1e-6f;
            float x = x_m1 - f1 * (x_m1 - x_m2) / fd;
            float step = fabsf(x - x_m1);
            x_m2 = x_m1;
            x_m1 = x;
            done = (step < 1e-6f);
        }
        kern[tid] = __expf(-0.01f * (un + x_m1));
    }
    if (wid >= 4) {
        const unsigned short* lut = (const unsigned short*)(sm + SM_LUT);
        for (int m = wid - 4; m < MB; m += 12) {
            char* hrow = sm + SM_R + m * H_STRIDE;
            #pragma unroll
            for (int it = 0; it < 5; ++it) {
                if (it == 4 && lid >= 16) break;
                int gw = it * 32 + lid;
                unsigned e = lut[gw];
                int i0  = e & 31;
                int i1b = (e >> 8) & 63;
                float a = coords[i0 * CT_STRIDE + m];
                float f[4];
                #pragma unroll
                for (int j = 0; j < 4; ++j)
                    f[j] = (i1b + j < 32) ? a * coords[(i1b + j) * CT_STRIDE + m] : 0.f;
                *(uint32_t*)(hrow + gw * 4) = pack4_e4m3(f[0], f[1], f[2], f[3]);
            }
        }
    }
    __syncthreads();

    // ---- main GEMM: 2 half-passes of 64 rows; 9 chunks, fp16 accumulators ----
    const char* vfw = (const char*)g_Vfrag + (uint32_t)((wid & 7) * 2048 + lid * 16);
    const float INV256 = 0.00390625f;

    #pragma unroll 1
    for (int hp = 0; hp < 2; ++hp) {
        const uint32_t hlane = smb + SM_R +
            (uint32_t)(hp * 64 + (wid >> 3) * 32 + (lid & 15)) * H_STRIDE +
            (uint32_t)((lid >> 4) * 16);

        uint32_t acc16[2][2][4][2];   // [mt][np][nt][reg]
        #pragma unroll
        for (int i = 0; i < 2; ++i)
            #pragma unroll
            for (int j = 0; j < 2; ++j)
                #pragma unroll
                for (int k = 0; k < 4; ++k) {
                    acc16[i][j][k][0] = 0u;
                    acc16[i][j][k][1] = 0u;
                }

        for (int c = 0; c < NCHUNK; ++c) {
            const uint4* vp0 = (const uint4*)(vfw + (size_t)c * 16384);
            const uint4* vp1 = (const uint4*)(vfw + (size_t)(c + NCHUNK) * 16384);
            const uint32_t koff = (uint32_t)(c * KCH);
            uint32_t a0[4], a1[4];
            ldsm4(a0, hlane + koff);
            ldsm4(a1, hlane + (uint32_t)(16 * H_STRIDE) + koff);
            {
                uint4 b0 = vp0[0], b1 = vp0[32];
                mma8h(acc16[0][0][0], a0, b0.x, b0.y);
                mma8h(acc16[0][0][1], a0, b0.z, b0.w);
                mma8h(acc16[0][0][2], a0, b1.x, b1.y);
                mma8h(acc16[0][0][3], a0, b1.z, b1.w);
                mma8h(acc16[1][0][0], a1, b0.x, b0.y);
                mma8h(acc16[1][0][1], a1, b0.z, b0.w);
                mma8h(acc16[1][0][2], a1, b1.x, b1.y);
                mma8h(acc16[1][0][3], a1, b1.z, b1.w);
            }
            {
                uint4 b0 = vp1[0], b1 = vp1[32];
                mma8h(acc16[0][1][0], a0, b0.x, b0.y);
                mma8h(acc16[0][1][1], a0, b0.z, b0.w);
                mma8h(acc16[0][1][2], a0, b1.x, b1.y);
                mma8h(acc16[0][1][3], a0, b1.z, b1.w);
                mma8h(acc16[1][1][0], a1, b0.x, b0.y);
                mma8h(acc16[1][1][1], a1, b0.z, b0.w);
                mma8h(acc16[1][1][2], a1, b1.x, b1.y);
                mma8h(acc16[1][1][3], a1, b1.z, b1.w);
            }
            ldsm4(a0, hlane + koff + 32);
            ldsm4(a1, hlane + (uint32_t)(16 * H_STRIDE) + koff + 32);
            {
                uint4 b0 = vp0[64], b1 = vp0[96];
                mma8h(acc16[0][0][0], a0, b0.x, b0.y);
                mma8h(acc16[0][0][1], a0, b0.z, b0.w);
                mma8h(acc16[0][0][2], a0, b1.x, b1.y);
                mma8h(acc16[0][0][3], a0, b1.z, b1.w);
                mma8h(acc16[1][0][0], a1, b0.x, b0.y);
                mma8h(acc16[1][0][1], a1, b0.z, b0.w);
                mma8h(acc16[1][0][2], a1, b1.x, b1.y);
                mma8h(acc16[1][0][3], a1, b1.z, b1.w);
            }
            {
                uint4 b0 = vp1[64], b1 = vp1[96];
                mma8h(acc16[0][1][0], a0, b0.x, b0.y);
                mma8h(acc16[0][1][1], a0, b0.z, b0.w);
                mma8h(acc16[0][1][2], a0, b1.x, b1.y);
                mma8h(acc16[0][1][3], a0, b1.z, b1.w);
                mma8h(acc16[1][1][0], a1, b0.x, b0.y);
                mma8h(acc16[1][1][1], a1, b0.z, b0.w);
                mma8h(acc16[1][1][2], a1, b1.x, b1.y);
                mma8h(acc16[1][1][3], a1, b1.z, b1.w);
            }
        }
        __syncthreads();   // all warps done with this half's H rows

        // ---- epilogue for this half: stage into the dead H rows ----
        const uint32_t stg = (uint32_t)(SM_R + hp * 37888);
        #pragma unroll
        for (int np = 0; np < 2; ++np) {
            {   // stage: conflict-free STS.32
                int r0 = (wid >> 3) * 32 + (lid >> 2);
                int cb = (wid & 7) * 32 + (lid & 3) * 2;
                #pragma unroll
                for (int mt = 0; mt < 2; ++mt)
                    #pragma unroll
                    for (int nt = 0; nt < 4; ++nt) {
                        int col = cb + nt * 8;
                        *(uint32_t*)(sm + stg + (r0 + mt * 16) * ES_STRIDE + col * 2) =
                            acc16[mt][np][nt][0];
                        *(uint32_t*)(sm + stg + (r0 + mt * 16 + 8) * ES_STRIDE + col * 2) =
                            acc16[mt][np][nt][1];
                    }
            }
            __syncthreads();
            {   // read + dense float4 gmem
                int rr = tid >> 3, q8 = tid & 7;
                int row = hp * 64 + rr;
                int gg = gid[row];
                float kr = kern[row];
                if (gg >= 0) {
                    const float4* zr4 = (const float4*)(Z_all + (size_t)gg * D + np * 256);
                    float4* or4 = (float4*)(out + (size_t)gg * D + np * 256);
                    #pragma unroll
                    for (int i = 0; i < 4; ++i) {
                        uint4 w = *(const uint4*)(sm + stg + rr * ES_STRIDE + i * 128 + q8 * 16);
                        float2 f0 = __half22float2(*(__half2*)&w.x);
                        float2 f1 = __half22float2(*(__half2*)&w.y);
                        float2 f2 = __half22float2(*(__half2*)&w.z);
                        float2 f3 = __half22float2(*(__half2*)&w.w);
                        int cg = np * 256 + i * 64 + q8 * 8;
                        int ci = i * 16 + q8 * 2;
                        float4 z0 = zr4[ci], z1 = zr4[ci + 1];
                        float4 o0, o1;
                        o0.x = z0.x + kr * (chg[cg]     + f0.x * INV256);
                        o0.y = z0.y + kr * (chg[cg + 1] + f0.y * INV256);
                        o0.z = z0.z + kr * (chg[cg + 2] + f1.x * INV256);
                        o0.w = z0.w + kr * (chg[cg + 3] + f1.y * INV256);
                        o1.x = z1.x + kr * (chg[cg + 4] + f2.x * INV256);
                        o1.y = z1.y + kr * (chg[cg + 5] + f2.y * INV256);
                        o1.z = z1.z + kr * (chg[cg + 6] + f3.x * INV256);
                        o1.w = z1.w + kr * (chg[cg + 7] + f3.y * INV256);
                        or4[ci]     = o0;
                        or4[ci + 1] = o1;
                    }
                }
            }
            if (np == 0) __syncthreads();
        }
    }
}

// ===================== launch =====================
extern "C" void kernel_launch(void* const* d_in, const int* in_sizes, int n_in,
                              void* d_out, int out_size) {
    const float* Z_all  = (const float*)d_in[0];
    const float* U      = (const float*)d_in[1];
    const float* V      = (const float*)d_in[2];
    const float* zmu    = (const float*)d_in[3];
    const float* xc     = (const float*)d_in[4];
    const int*   choice = (const int*)  d_in[5];
    float*       out    = (float*)d_out;
    const int Nc = in_sizes[5];

    if ((size_t)Nc * D != (size_t)in_sizes[0]) {
        cudaMemcpyAsync(d_out, Z_all, (size_t)in_sizes[0] * sizeof(float),
                        cudaMemcpyDeviceToDevice, 0);
    }

    prep_kernel<<<369, 256>>>(U, V, zmu, xc);

    cudaFuncSetAttribute(glayer_fused, cudaFuncAttributeMaxDynamicSharedMemorySize, SM_TOTAL);
    int nblocks = (Nc + MB - 1) / MB;
    glayer_fused<<<nblocks, NTHREADS, SM_TOTAL>>>(Z_all, choice, out, Nc);
}

// round 15
// speedup vs baseline: 1.4121x; 1.4121x over previous
#include <cuda_runtime.h>
#include <cuda_bf16.h>
#include <cuda_fp16.h>
#include <cuda_fp8.h>
#include <math.h>
#include <stdint.h>

#define D        512
#define KK       32
#define PP       528
#define MB       64                // rows per CTA
#define KCH      64
#define NCHUNK   9
#define NTHREADS 512

#define H_STRIDE 592               // 576 + 16; /16 odd
#define ZQ_STRIDE 272
#define U_STRIDE 80
#define UQ_BYTES  (128 * U_STRIDE)
#define CT_STRIDE 65               // coordsT word stride
#define ES_STRIDE 528              // epilogue stage row bytes

// ---------- smem ----------
#define SM_GID   0
#define SM_KERN  256
#define SM_CHG   512
#define SM_ZMU   2560
#define SM_LUT   4608              // 144 u16 word-lut (288B; pad to 1088 slot)
#define SM_PBUF  5696
#define SM_COORD 7744              // 32*65*4 = 8320
#define SM_R     16192             // phase1 ZQ+UQ | phase2 H(37888) | phase3 stage
#define SM_UQ    33600
#define SM_TOTAL 54080

__device__ float g_change[D];
__device__ float g_zmu[D];
__device__ float g_xcU[KK];
__device__ float g_dU[KK];
__device__ __align__(8) unsigned short g_wlut[144];            // i0 | (i1base<<8)
__device__ __align__(16) unsigned char g_Ubf[512 * U_STRIDE];
// V fragments, word-repacked to the row-aligned H layout
__device__ __align__(16) unsigned char g_Vfrag[18 * 16384];    // 288KB

__device__ __forceinline__ uint32_t smem_u32(const void* p) {
    uint32_t a;
    asm("{ .reg .u64 t; cvta.to.shared.u64 t, %1; cvt.u32.u64 %0, t; }" : "=r"(a) : "l"(p));
    return a;
}
__device__ __forceinline__ void ldsm4(uint32_t* r, uint32_t a) {
    asm volatile("ldmatrix.sync.aligned.m8n8.x4.shared.b16 {%0,%1,%2,%3}, [%4];"
                 : "=r"(r[0]), "=r"(r[1]), "=r"(r[2]), "=r"(r[3]) : "r"(a));
}
__device__ __forceinline__ void ldsm4t(uint32_t* r, uint32_t a) {
    asm volatile("ldmatrix.sync.aligned.m8n8.x4.trans.shared.b16 {%0,%1,%2,%3}, [%4];"
                 : "=r"(r[0]), "=r"(r[1]), "=r"(r[2]), "=r"(r[3]) : "r"(a));
}
__device__ __forceinline__ void mma16816(float* c, const uint32_t* a, const uint32_t* b) {
    asm volatile("mma.sync.aligned.m16n8k16.row.col.f32.bf16.bf16.f32 "
                 "{%0,%1,%2,%3}, {%4,%5,%6,%7}, {%8,%9}, {%0,%1,%2,%3};"
                 : "+f"(c[0]), "+f"(c[1]), "+f"(c[2]), "+f"(c[3])
                 : "r"(a[0]), "r"(a[1]), "r"(a[2]), "r"(a[3]), "r"(b[0]), "r"(b[1]));
}
__device__ __forceinline__ void mma8h(uint32_t* c, const uint32_t* a, uint32_t b0, uint32_t b1) {
    asm volatile("mma.sync.aligned.m16n8k32.row.col.f16.e4m3.e4m3.f16 "
                 "{%0,%1}, {%2,%3,%4,%5}, {%6,%7}, {%0,%1};"
                 : "+r"(c[0]), "+r"(c[1])
                 : "r"(a[0]), "r"(a[1]), "r"(a[2]), "r"(a[3]), "r"(b0), "r"(b1));
}
__device__ __forceinline__ uint32_t pack4_e4m3(float f0, float f1, float f2, float f3) {
    uint32_t r;
    asm("{\n\t.reg .b16 lo, hi;\n\t"
        "cvt.rn.satfinite.e4m3x2.f32 lo, %2, %1;\n\t"
        "cvt.rn.satfinite.e4m3x2.f32 hi, %4, %3;\n\t"
        "mov.b32 %0, {lo, hi};\n\t}"
        : "=r"(r) : "f"(f0), "f"(f1), "f"(f2), "f"(f3));
    return r;
}
__device__ __forceinline__ void cp16(uint32_t saddr, const void* g) {
    asm volatile("cp.async.cg.shared.global [%0], [%1], 16;" :: "r"(saddr), "l"(g));
}
__device__ __forceinline__ void cp_commit() {
    asm volatile("cp.async.commit_group;" ::: "memory");
}
template <int N>
__device__ __forceinline__ void cp_wait() {
    asm volatile("cp.async.wait_group %0;" :: "n"(N) : "memory");
}

// word g -> (i0, i1base, pstart): words are 4-consecutive runs inside triu rows
__device__ __forceinline__ void wordinfo(int g, int* i0, int* i1b, int* pstart) {
    int acc = 0, rs = 0;
    #pragma unroll 1
    for (int i = 0; i < 32; ++i) {
        int wr = (35 - i) >> 2;            // words in row i (len 32-i)
        if (g < acc + wr) {
            int k = g - acc;
            *i0 = i;
            *i1b = i + 4 * k;
            *pstart = rs + 4 * k;
            return;
        }
        acc += wr;
        rs += 32 - i;
    }
    *i0 = 0; *i1b = 32; *pstart = 0;
}

// ===================== prep =====================
__global__ void prep_kernel(const float* __restrict__ U,
                            const float* __restrict__ V,
                            const float* __restrict__ zmu,
                            const float* __restrict__ xc) {
    int b = blockIdx.x, t = threadIdx.x;
    if (b < 288) {
        int idx = b * 256 + t;                 // one fragment u32 word
        int l    = (idx >> 2) & 31;
        int jj   = idx & 3;
        int q    = (idx >> 7) & 1;
        int ks   = (idx >> 8) & 1;
        int ngrp = (idx >> 9) & 7;
        int tt   = idx >> 12;
        int i    = 8 * jj + (l >> 2);
        int nl   = ngrp * 32 + q * 16 + (i & 7) + 8 * ((i >> 4) & 1);
        int koff = ((i >> 3) & 1) * 16 + ks * 32 + (l & 3) * 4;
        int c  = tt % NCHUNK, np = tt / NCHUNK;
        int d  = np * 256 + nl;
        int g  = (c * KCH + koff) >> 2;        // H word index
        int i0, i1b, ps;
        wordinfo(g, &i0, &i1b, &ps);
        float f[4];
        #pragma unroll
        for (int byte = 0; byte < 4; ++byte)
            f[byte] = (i1b + byte < 32) ? V[(size_t)d * PP + ps + byte] * 256.f : 0.f;
        *(uint32_t*)(g_Vfrag + (size_t)idx * 4) = pack4_e4m3(f[0], f[1], f[2], f[3]);
        return;
    }
    if (b < 368) {
        int e = (b - 288) * 256 + t;
        int k = e / 40, n = e - k * 40;
        float v = (n < KK) ? U[k * KK + n] : 0.f;
        *(__nv_bfloat16*)(g_Ubf + k * U_STRIDE + n * 2) = __float2bfloat16(v);
        return;
    }
    __shared__ float pa[256], pb[256], sdiff[KK];
    {
        int j = t & 31, seg = t >> 5;
        float a = 0.f, bb = 0.f;
        for (int i = 0; i < 64; ++i) {
            int d = seg * 64 + i;
            float u = U[d * KK + j];
            a = fmaf(zmu[d], u, a);
            bb = fmaf(xc[d], u, bb);
        }
        pa[t] = a; pb[t] = bb;
    }
    __syncthreads();
    if (t < KK) {
        float sa = 0.f, sb = 0.f;
        for (int s = 0; s < 8; ++s) { sa += pa[s * 32 + t]; sb += pb[s * 32 + t]; }
        g_xcU[t] = sb;
        g_dU[t]  = sb - sa;
        sdiff[t] = sb - sa;
    }
    __syncthreads();
    for (int d = t; d < D; d += 256) {
        float s = 0.f;
        for (int j = 0; j < KK; ++j) s = fmaf(sdiff[j], U[d * KK + j], s);
        g_change[d] = xc[d] - zmu[d] - s;
        g_zmu[d] = zmu[d];
    }
    if (t < 144) {
        int i0, i1b, ps;
        wordinfo(t, &i0, &i1b, &ps);
        g_wlut[t] = (unsigned short)(i0 | (i1b << 8));
    }
}

// ===================== fused main kernel (M=64, occ 2) ==========
__global__ __launch_bounds__(NTHREADS, 2)
void glayer_fused(const float* __restrict__ Z_all,
                  const int*   __restrict__ choice,
                  float*       __restrict__ out,
                  int Nc) {
    extern __shared__ __align__(16) char sm[];
    const uint32_t smb = smem_u32(sm);
    int*   gid    = (int*)(sm + SM_GID);
    float* kern   = (float*)(sm + SM_KERN);
    float* chg    = (float*)(sm + SM_CHG);
    float* zmus   = (float*)(sm + SM_ZMU);
    float* pbuf   = (float*)(sm + SM_PBUF);
    float* coords = (float*)(sm + SM_COORD);   // coordsT[j][m], stride 65 words

    const int tid = threadIdx.x;
    const int wid = tid >> 5;
    const int lid = tid & 31;
    const int n0  = blockIdx.x * MB;

    // U quarter 0 async copy up front
    {
        const char* usrc = (const char*)g_Ubf;
        if (tid < UQ_BYTES / 16) cp16(smb + SM_UQ + tid * 16, usrc + (size_t)tid * 16);
        if (tid < UQ_BYTES / 16 - 512)
            cp16(smb + SM_UQ + (tid + 512) * 16, usrc + (size_t)(tid + 512) * 16);
        cp_commit();
    }

    if (tid < MB) {
        int n = n0 + tid;
        gid[tid] = (n < Nc) ? choice[n] : -1;
    }
    chg[tid]  = g_change[tid];
    zmus[tid] = g_zmu[tid];
    if (tid < 72) ((uint32_t*)(sm + SM_LUT))[tid] = ((const uint32_t*)g_wlut)[tid];
    __syncthreads();

    // ---- phase 1: gather in 4 k-quarters + ZU mma ----
    const int r  = tid >> 3, s8 = tid & 7;
    const int g  = gid[r];
    const float4* zrowg = (const float4*)(Z_all + (size_t)(g < 0 ? 0 : g) * D) + s8 * 4;
    char* zrow = sm + SM_R + r * ZQ_STRIDE + s8 * 32;

    const int zr0 = (wid & 3) * 16;
    const int zch = (wid >> 2) & 1;
    const uint32_t zbase = smb + SM_R + (uint32_t)(zr0 + (lid & 15)) * ZQ_STRIDE +
                           (uint32_t)((lid >> 4) * 16);
    const uint32_t ulane = (uint32_t)((lid & 7) + 8 * ((lid >> 3) & 1)) * U_STRIDE +
                           (uint32_t)(zch * 16 + 8 * (lid >> 4)) * 2;

    float zu[2][4];
    #pragma unroll
    for (int i = 0; i < 2; ++i)
        #pragma unroll
        for (int j = 0; j < 4; ++j) zu[i][j] = 0.f;

    float accn = 0.f;
    for (int q = 0; q < 4; ++q) {
        #pragma unroll
        for (int i = 0; i < 4; ++i) {
            float4 z = make_float4(0.f, 0.f, 0.f, 0.f);
            if (g >= 0) z = zrowg[q * 32 + i];
            int d0 = q * 128 + s8 * 16 + i * 4;
            float a0 = z.x - zmus[d0], a1 = z.y - zmus[d0 + 1];
            float a2 = z.z - zmus[d0 + 2], a3 = z.w - zmus[d0 + 3];
            accn = fmaf(a0, a0, fmaf(a1, a1, fmaf(a2, a2, fmaf(a3, a3, accn))));
            __nv_bfloat162 p0 = __floats2bfloat162_rn(z.x, z.y);
            __nv_bfloat162 p1 = __floats2bfloat162_rn(z.z, z.w);
            *(uint32_t*)(zrow + i * 8)     = *(uint32_t*)&p0;
            *(uint32_t*)(zrow + i * 8 + 4) = *(uint32_t*)&p1;
        }
        if (q == 3) pbuf[tid] = accn;
        if (q < 3) {
            const char* usrc = (const char*)g_Ubf + (size_t)(q + 1) * UQ_BYTES;
            uint32_t ud = smb + SM_UQ + (uint32_t)(((q + 1) & 1) * UQ_BYTES);
            if (tid < UQ_BYTES / 16) cp16(ud + tid * 16, usrc + (size_t)tid * 16);
            if (tid < UQ_BYTES / 16 - 512)
                cp16(ud + (tid + 512) * 16, usrc + (size_t)(tid + 512) * 16);
            cp_commit();
            cp_wait<1>();
        } else {
            cp_wait<0>();
        }
        __syncthreads();
        if (wid < 8) {
            uint32_t ub = smb + SM_UQ + (uint32_t)((q & 1) * UQ_BYTES) + ulane;
            #pragma unroll
            for (int ks = 0; ks < 8; ++ks) {
                uint32_t a[4], b[4];
                ldsm4(a, zbase + (uint32_t)(ks * 32));
                ldsm4t(b, ub + (uint32_t)(ks * 16) * U_STRIDE);
                mma16816(zu[0], a, b);
                mma16816(zu[1], a, b + 2);
            }
        }
        __syncthreads();
    }

    // coordsT[c][m] = ZU - xcU
    if (wid < 8) {
        int r0 = zr0 + (lid >> 2);
        int c0 = (lid & 3) * 2;
        #pragma unroll
        for (int nt = 0; nt < 2; ++nt) {
            int c = zch * 16 + nt * 8 + c0;
            coords[c * CT_STRIDE + r0]           = zu[nt][0] - g_xcU[c];
            coords[(c + 1) * CT_STRIDE + r0]     = zu[nt][1] - g_xcU[c + 1];
            coords[c * CT_STRIDE + r0 + 8]       = zu[nt][2] - g_xcU[c];
            coords[(c + 1) * CT_STRIDE + r0 + 8] = zu[nt][3] - g_xcU[c + 1];
        }
    }
    __syncthreads();

    // ---- secant (threads 0..63) || row-aligned H build (warps 2..15) ----
    if (tid < MB) {
        float un = 0.f;
        #pragma unroll
        for (int j = 0; j < KK; ++j) {
            float v = coords[j * CT_STRIDE + tid] + g_dU[j];
            un = fmaf(v, v, un);
        }
        float zn = 0.f;
        #pragma unroll
        for (int k = 0; k < 8; ++k) zn += pbuf[tid * 8 + k];
        float C = zn - un;
        float E = __expf(-0.01f * un);
        float x_m2 = C * 0.999f;
        float x_m1 = C;
        bool done = false;
        for (int it = 0; it < 100; ++it) {
            if (done) break;
            float t1 = 1.f - E * __expf(-0.01f * x_m1);
            float f1 = t1 * t1 * x_m1 - C;
            float t2 = 1.f - E * __expf(-0.01f * x_m2);
            float f2 = t2 * t2 * x_m2 - C;
            float fd = f1 - f2;
            if (fabsf(fd) < 1e-6f) fd = (fd >= 0.f) ? 1e-6f : -1e-6f;
            float x = x_m1 - f1 * (x_m1 - x_m2) / fd;
            float step = fabsf(x - x_m1);
            x_m2 = x_m1;
            x_m1 = x;
            done = (step < 1e-6f);
        }
        kern[tid] = __expf(-0.01f * (un + x_m1));
    }
    if (wid >= 2) {
        const unsigned short* lut = (const unsigned short*)(sm + SM_LUT);
        for (int m = wid - 2; m < MB; m += 14) {
            char* hrow = sm + SM_R + m * H_STRIDE;
            #pragma unroll
            for (int it = 0; it < 5; ++it) {
                if (it == 4 && lid >= 16) break;
                int gw = it * 32 + lid;
                unsigned e = lut[gw];
                int i0  = e & 31;
                int i1b = (e >> 8) & 63;
                float a = coords[i0 * CT_STRIDE + m];
                float f[4];
                #pragma unroll
                for (int j = 0; j < 4; ++j)
                    f[j] = (i1b + j < 32) ? a * coords[(i1b + j) * CT_STRIDE + m] : 0.f;
                *(uint32_t*)(hrow + gw * 4) = pack4_e4m3(f[0], f[1], f[2], f[3]);
            }
        }
    }
    __syncthreads();

    // ---- main GEMM: 9 chunks, both N-halves, fp16 accumulators ----
    const int mg = (wid >> 3) * 32;
    const uint32_t hlane = smb + SM_R + (uint32_t)(mg + (lid & 15)) * H_STRIDE +
                           (uint32_t)((lid >> 4) * 16);
    const char* vfw = (const char*)g_Vfrag + (uint32_t)((wid & 7) * 2048 + lid * 16);
    const float INV256 = 0.00390625f;

    uint32_t acc16[2][2][4][2];   // [mt][np][nt][reg]
    #pragma unroll
    for (int i = 0; i < 2; ++i)
        #pragma unroll
        for (int j = 0; j < 2; ++j)
            #pragma unroll
            for (int k = 0; k < 4; ++k) {
                acc16[i][j][k][0] = 0u;
                acc16[i][j][k][1] = 0u;
            }

    for (int c = 0; c < NCHUNK; ++c) {
        const uint4* vp0 = (const uint4*)(vfw + (size_t)c * 16384);
        const uint4* vp1 = (const uint4*)(vfw + (size_t)(c + NCHUNK) * 16384);
        const uint32_t koff = (uint32_t)(c * KCH);
        uint32_t a0[4], a1[4];
        ldsm4(a0, hlane + koff);
        ldsm4(a1, hlane + (uint32_t)(16 * H_STRIDE) + koff);
        {
            uint4 b0 = vp0[0], b1 = vp0[32];
            mma8h(acc16[0][0][0], a0, b0.x, b0.y);
            mma8h(acc16[0][0][1], a0, b0.z, b0.w);
            mma8h(acc16[0][0][2], a0, b1.x, b1.y);
            mma8h(acc16[0][0][3], a0, b1.z, b1.w);
            mma8h(acc16[1][0][0], a1, b0.x, b0.y);
            mma8h(acc16[1][0][1], a1, b0.z, b0.w);
            mma8h(acc16[1][0][2], a1, b1.x, b1.y);
            mma8h(acc16[1][0][3], a1, b1.z, b1.w);
        }
        {
            uint4 b0 = vp1[0], b1 = vp1[32];
            mma8h(acc16[0][1][0], a0, b0.x, b0.y);
            mma8h(acc16[0][1][1], a0, b0.z, b0.w);
            mma8h(acc16[0][1][2], a0, b1.x, b1.y);
            mma8h(acc16[0][1][3], a0, b1.z, b1.w);
            mma8h(acc16[1][1][0], a1, b0.x, b0.y);
            mma8h(acc16[1][1][1], a1, b0.z, b0.w);
            mma8h(acc16[1][1][2], a1, b1.x, b1.y);
            mma8h(acc16[1][1][3], a1, b1.z, b1.w);
        }
        ldsm4(a0, hlane + koff + 32);
        ldsm4(a1, hlane + (uint32_t)(16 * H_STRIDE) + koff + 32);
        {
            uint4 b0 = vp0[64], b1 = vp0[96];
            mma8h(acc16[0][0][0], a0, b0.x, b0.y);
            mma8h(acc16[0][0][1], a0, b0.z, b0.w);
            mma8h(acc16[0][0][2], a0, b1.x, b1.y);
            mma8h(acc16[0][0][3], a0, b1.z, b1.w);
            mma8h(acc16[1][0][0], a1, b0.x, b0.y);
            mma8h(acc16[1][0][1], a1, b0.z, b0.w);
            mma8h(acc16[1][0][2], a1, b1.x, b1.y);
            mma8h(acc16[1][0][3], a1, b1.z, b1.w);
        }
        {
            uint4 b0 = vp1[64], b1 = vp1[96];
            mma8h(acc16[0][1][0], a0, b0.x, b0.y);
            mma8h(acc16[0][1][1], a0, b0.z, b0.w);
            mma8h(acc16[0][1][2], a0, b1.x, b1.y);
            mma8h(acc16[0][1][3], a0, b1.z, b1.w);
            mma8h(acc16[1][1][0], a1, b0.x, b0.y);
            mma8h(acc16[1][1][1], a1, b0.z, b0.w);
            mma8h(acc16[1][1][2], a1, b1.x, b1.y);
            mma8h(acc16[1][1][3], a1, b1.z, b1.w);
        }
    }
    __syncthreads();    // H region dead; reuse for epilogue staging

    // ---- epilogue: stage fp16 accs to smem, then fully coalesced gmem ----
    #pragma unroll
    for (int np = 0; np < 2; ++np) {
        {
            int r0 = mg + (lid >> 2);
            int cb = (wid & 7) * 32 + (lid & 3) * 2;
            #pragma unroll
            for (int mt = 0; mt < 2; ++mt)
                #pragma unroll
                for (int nt = 0; nt < 4; ++nt) {
                    int col = cb + nt * 8;
                    *(uint32_t*)(sm + SM_R + (r0 + mt * 16) * ES_STRIDE + col * 2) =
                        acc16[mt][np][nt][0];
                    *(uint32_t*)(sm + SM_R + (r0 + mt * 16 + 8) * ES_STRIDE + col * 2) =
                        acc16[mt][np][nt][1];
                }
        }
        __syncthreads();
        {
            int rr = tid >> 3, q8 = tid & 7;
            int gg = gid[rr];
            float kr = kern[rr];
            if (gg >= 0) {
                const float4* zr4 = (const float4*)(Z_all + (size_t)gg * D + np * 256);
                float4* or4 = (float4*)(out + (size_t)gg * D + np * 256);
                #pragma unroll
                for (int i = 0; i < 4; ++i) {
                    uint4 w = *(const uint4*)(sm + SM_R + rr * ES_STRIDE + i * 128 + q8 * 16);
                    float2 f0 = __half22float2(*(__half2*)&w.x);
                    float2 f1 = __half22float2(*(__half2*)&w.y);
                    float2 f2 = __half22float2(*(__half2*)&w.z);
                    float2 f3 = __half22float2(*(__half2*)&w.w);
                    int cg = np * 256 + i * 64 + q8 * 8;
                    int ci = i * 16 + q8 * 2;
                    float4 z0 = zr4[ci], z1 = zr4[ci + 1];
                    float4 o0, o1;
                    o0.x = z0.x + kr * (chg[cg]     + f0.x * INV256);
                    o0.y = z0.y + kr * (chg[cg + 1] + f0.y * INV256);
                    o0.z = z0.z + kr * (chg[cg + 2] + f1.x * INV256);
                    o0.w = z0.w + kr * (chg[cg + 3] + f1.y * INV256);
                    o1.x = z1.x + kr * (chg[cg + 4] + f2.x * INV256);
                    o1.y = z1.y + kr * (chg[cg + 5] + f2.y * INV256);
                    o1.z = z1.z + kr * (chg[cg + 6] + f3.x * INV256);
                    o1.w = z1.w + kr * (chg[cg + 7] + f3.y * INV256);
                    or4[ci]     = o0;
                    or4[ci + 1] = o1;
                }
            }
        }
        if (np == 0) __syncthreads();
    }
}

// ===================== launch =====================
extern "C" void kernel_launch(void* const* d_in, const int* in_sizes, int n_in,
                              void* d_out, int out_size) {
    const float* Z_all  = (const float*)d_in[0];
    const float* U      = (const float*)d_in[1];
    const float* V      = (const float*)d_in[2];
    const float* zmu    = (const float*)d_in[3];
    const float* xc     = (const float*)d_in[4];
    const int*   choice = (const int*)  d_in[5];
    float*       out    = (float*)d_out;
    const int Nc = in_sizes[5];

    if ((size_t)Nc * D != (size_t)in_sizes[0]) {
        cudaMemcpyAsync(d_out, Z_all, (size_t)in_sizes[0] * sizeof(float),
                        cudaMemcpyDeviceToDevice, 0);
    }

    prep_kernel<<<369, 256>>>(U, V, zmu, xc);

    cudaFuncSetAttribute(glayer_fused, cudaFuncAttributeMaxDynamicSharedMemorySize, SM_TOTAL);
    int nblocks = (Nc + MB - 1) / MB;
    glayer_fused<<<nblocks, NTHREADS, SM_TOTAL>>>(Z_all, choice, out, Nc);
}